// round 1
// baseline (speedup 1.0000x reference)
#include <cuda_runtime.h>
#include <math.h>

// Problem constants
constexpr int B = 4;
constexpr int L = 2048;
constexpr int S = 2048;
constexpr int E = 1024;
constexpr int H = 16;
constexpr int D = 64;
constexpr float SCALING = 0.125f;   // D^-0.5 = 64^-0.5

// ---------------- device scratch (no allocations allowed) ----------------
__device__ float g_q[(size_t)B * H * L * D];    // [B,H,L,D]
__device__ float g_k[(size_t)B * H * S * D];    // [B,H,S,D]
__device__ float g_v[(size_t)B * H * S * D];    // [B,H,S,D]
__device__ float g_attn[(size_t)B * L * E];     // [B,L,E]  (attention output)
__device__ float g_mb[(size_t)L * S];           // mask + bias, [L,S]

// ---------------- mask+bias precompute ----------------
__global__ void mb_kernel(const float* __restrict__ attn_bias,
                          const float* __restrict__ attn_mask) {
    size_t i = ((size_t)blockIdx.x * blockDim.x + threadIdx.x) * 4;
    float4 a = *(const float4*)(attn_mask + i);
    float4 c = *(const float4*)(attn_bias + i);
    float4 r;
    r.x = a.x + c.x; r.y = a.y + c.y; r.z = a.z + c.z; r.w = a.w + c.w;
    *(float4*)(g_mb + i) = r;
}

// ---------------- SGEMM tile engine: C(128x128) += A(128xK) * W(128xK)^T ----
constexpr int BM = 128, BN = 128, BK = 16, PAD = 4;

__device__ __forceinline__ void gemm_tile(const float* __restrict__ A,   // offset to row m0, lda=E
                                          const float* __restrict__ W,   // offset to row n0, ldw=E
                                          float (&acc)[8][8],
                                          float (*As)[BM + PAD],
                                          float (*Ws)[BN + PAD]) {
    const int tid = threadIdx.x;
    const int tx = tid & 15, ty = tid >> 4;

    for (int k0 = 0; k0 < E; k0 += BK) {
        #pragma unroll
        for (int it = 0; it < 2; ++it) {
            int id = tid * 2 + it;        // 0..511
            int r = id >> 2;              // 0..127
            int c = (id & 3) << 2;        // 0,4,8,12
            float4 av = *(const float4*)(A + (size_t)r * E + k0 + c);
            As[c + 0][r] = av.x; As[c + 1][r] = av.y;
            As[c + 2][r] = av.z; As[c + 3][r] = av.w;
            float4 wv = *(const float4*)(W + (size_t)r * E + k0 + c);
            Ws[c + 0][r] = wv.x; Ws[c + 1][r] = wv.y;
            Ws[c + 2][r] = wv.z; Ws[c + 3][r] = wv.w;
        }
        __syncthreads();
        #pragma unroll
        for (int k = 0; k < BK; ++k) {
            float4 a0 = *(const float4*)&As[k][ty * 8];
            float4 a1 = *(const float4*)&As[k][ty * 8 + 4];
            float4 b0 = *(const float4*)&Ws[k][tx * 8];
            float4 b1 = *(const float4*)&Ws[k][tx * 8 + 4];
            float a[8] = {a0.x, a0.y, a0.z, a0.w, a1.x, a1.y, a1.z, a1.w};
            float bb[8] = {b0.x, b0.y, b0.z, b0.w, b1.x, b1.y, b1.z, b1.w};
            #pragma unroll
            for (int i = 0; i < 8; ++i)
                #pragma unroll
                for (int j = 0; j < 8; ++j)
                    acc[i][j] += a[i] * bb[j];
        }
        __syncthreads();
    }
}

// ---------------- fused QKV projection -----------------------------------
// grid: (M/128 = 64, 3072/128 = 24). Slice 0 -> q (scaled), 1 -> k, 2 -> v.
__global__ void __launch_bounds__(256) qkv_gemm(const float* __restrict__ q_in,
                                                const float* __restrict__ k_in,
                                                const float* __restrict__ v_in,
                                                const float* __restrict__ Wqkv,
                                                const float* __restrict__ bqkv) {
    __shared__ float As[BK][BM + PAD];
    __shared__ float Ws[BK][BN + PAD];

    const int m0 = blockIdx.x * BM;      // over B*L = 8192
    const int n0 = blockIdx.y * BN;      // over 3*E = 3072
    const int slice = n0 >> 10;

    const float* Aall = (slice == 0) ? q_in : ((slice == 1) ? k_in : v_in);
    const float* A = Aall + (size_t)m0 * E;
    const float* W = Wqkv + (size_t)n0 * E;

    float acc[8][8] = {};
    gemm_tile(A, W, acc, As, Ws);

    float* dst = (slice == 0) ? g_q : ((slice == 1) ? g_k : g_v);
    const float scale = (slice == 0) ? SCALING : 1.0f;
    const int tx = threadIdx.x & 15, ty = threadIdx.x >> 4;

    #pragma unroll
    for (int i = 0; i < 8; ++i) {
        int m = m0 + ty * 8 + i;
        int bb = m >> 11;           // / L
        int ll = m & (L - 1);
        #pragma unroll
        for (int j = 0; j < 8; ++j) {
            int ng = n0 + tx * 8 + j;
            int nn = ng & (E - 1);
            int hh = nn >> 6;
            int dd = nn & 63;
            dst[(((size_t)bb * H + hh) * L + ll) * D + dd] = (acc[i][j] + bqkv[ng]) * scale;
        }
    }
}

// ---------------- output projection ---------------------------------------
// grid: (64, 8)
__global__ void __launch_bounds__(256) out_gemm(const float* __restrict__ Wo,
                                                const float* __restrict__ bo,
                                                float* __restrict__ out) {
    __shared__ float As[BK][BM + PAD];
    __shared__ float Ws[BK][BN + PAD];

    const int m0 = blockIdx.x * BM;
    const int n0 = blockIdx.y * BN;
    const float* A = g_attn + (size_t)m0 * E;
    const float* W = Wo + (size_t)n0 * E;

    float acc[8][8] = {};
    gemm_tile(A, W, acc, As, Ws);

    const int tx = threadIdx.x & 15, ty = threadIdx.x >> 4;
    #pragma unroll
    for (int i = 0; i < 8; ++i) {
        int m = m0 + ty * 8 + i;
        #pragma unroll
        for (int j4 = 0; j4 < 2; ++j4) {
            int n = n0 + tx * 8 + j4 * 4;
            float4 r;
            r.x = acc[i][j4 * 4 + 0] + bo[n + 0];
            r.y = acc[i][j4 * 4 + 1] + bo[n + 1];
            r.z = acc[i][j4 * 4 + 2] + bo[n + 2];
            r.w = acc[i][j4 * 4 + 3] + bo[n + 3];
            *(float4*)(out + (size_t)m * E + n) = r;
        }
    }
}

// ---------------- flash attention (fp32, online softmax) ------------------
// grid: (L/64 = 32, H = 16, B = 4); 256 threads; dyn smem = 4 * 64*68 floats
constexpr int LDT = 68;

__global__ void __launch_bounds__(256) attn_kernel() {
    extern __shared__ float sm[];
    float (*Qs)[LDT] = (float(*)[LDT])(sm);               // [d][r]
    float (*Ks)[LDT] = (float(*)[LDT])(sm + 64 * LDT);    // [d][s]
    float (*Vs)[LDT] = (float(*)[LDT])(sm + 2 * 64 * LDT);// [s][d]
    float (*Ps)[LDT] = (float(*)[LDT])(sm + 3 * 64 * LDT);// [s][r]

    const int tid = threadIdx.x;
    const int tx = tid & 15, ty = tid >> 4;
    const int l0 = blockIdx.x * 64;
    const int h = blockIdx.y, b = blockIdx.z;

    const float* Qg = g_q + (((size_t)b * H + h) * L + l0) * D;
    const float* Kg = g_k + (((size_t)b * H + h) * S) * D;
    const float* Vg = g_v + (((size_t)b * H + h) * S) * D;

    // load Q tile (transpose to d-major)
    #pragma unroll
    for (int it = 0; it < 4; ++it) {
        int id = tid + it * 256;
        int r = id >> 4;
        int c = (id & 15) << 2;
        float4 v = *(const float4*)(Qg + (size_t)r * D + c);
        Qs[c + 0][r] = v.x; Qs[c + 1][r] = v.y;
        Qs[c + 2][r] = v.z; Qs[c + 3][r] = v.w;
    }

    float o[4][4] = {};
    float mrow[4] = {-1e30f, -1e30f, -1e30f, -1e30f};
    float lrow[4] = {};

    for (int j0 = 0; j0 < S; j0 += 64) {
        __syncthreads();   // prev PV done (and Q load done on first iter)
        #pragma unroll
        for (int it = 0; it < 4; ++it) {
            int id = tid + it * 256;
            int r = id >> 4;
            int c = (id & 15) << 2;
            float4 kv = *(const float4*)(Kg + (size_t)(j0 + r) * D + c);
            Ks[c + 0][r] = kv.x; Ks[c + 1][r] = kv.y;
            Ks[c + 2][r] = kv.z; Ks[c + 3][r] = kv.w;
            float4 vv = *(const float4*)(Vg + (size_t)(j0 + r) * D + c);
            *(float4*)&Vs[r][c] = vv;
        }
        __syncthreads();

        // scores: S = Q K^T  (4x4 per thread)
        float sacc[4][4] = {};
        #pragma unroll
        for (int d = 0; d < 64; ++d) {
            float4 qa = *(const float4*)&Qs[d][ty << 2];
            float4 kb = *(const float4*)&Ks[d][tx << 2];
            float av[4] = {qa.x, qa.y, qa.z, qa.w};
            float bv[4] = {kb.x, kb.y, kb.z, kb.w};
            #pragma unroll
            for (int i = 0; i < 4; ++i)
                #pragma unroll
                for (int j = 0; j < 4; ++j)
                    sacc[i][j] += av[i] * bv[j];
        }

        // + (mask + bias)
        const float* mbrow = g_mb + (size_t)(l0 + (ty << 2)) * S + j0 + (tx << 2);
        #pragma unroll
        for (int i = 0; i < 4; ++i) {
            float4 mv = *(const float4*)(mbrow + (size_t)i * S);
            sacc[i][0] += mv.x; sacc[i][1] += mv.y;
            sacc[i][2] += mv.z; sacc[i][3] += mv.w;
        }

        // online softmax per row (row split across 16 lanes of same ty)
        #pragma unroll
        for (int i = 0; i < 4; ++i) {
            float tm = fmaxf(fmaxf(sacc[i][0], sacc[i][1]),
                             fmaxf(sacc[i][2], sacc[i][3]));
            #pragma unroll
            for (int off = 8; off > 0; off >>= 1)
                tm = fmaxf(tm, __shfl_xor_sync(0xffffffffu, tm, off));
            float mnew = fmaxf(mrow[i], tm);
            float corr = __expf(mrow[i] - mnew);
            mrow[i] = mnew;
            float ps = 0.f;
            #pragma unroll
            for (int j = 0; j < 4; ++j) {
                float p = __expf(sacc[i][j] - mnew);
                sacc[i][j] = p;
                ps += p;
            }
            #pragma unroll
            for (int off = 8; off > 0; off >>= 1)
                ps += __shfl_xor_sync(0xffffffffu, ps, off);
            lrow[i] = lrow[i] * corr + ps;
            #pragma unroll
            for (int j = 0; j < 4; ++j) o[i][j] *= corr;
        }

        // stage P (s-major) for the PV GEMM
        #pragma unroll
        for (int i = 0; i < 4; ++i)
            #pragma unroll
            for (int j = 0; j < 4; ++j)
                Ps[(tx << 2) + j][(ty << 2) + i] = sacc[i][j];
        __syncthreads();

        // O += P V
        #pragma unroll
        for (int s = 0; s < 64; ++s) {
            float4 pa = *(const float4*)&Ps[s][ty << 2];
            float4 vb = *(const float4*)&Vs[s][tx << 2];
            float av[4] = {pa.x, pa.y, pa.z, pa.w};
            float bv[4] = {vb.x, vb.y, vb.z, vb.w};
            #pragma unroll
            for (int i = 0; i < 4; ++i)
                #pragma unroll
                for (int j = 0; j < 4; ++j)
                    o[i][j] += av[i] * bv[j];
        }
    }

    // normalize + write to [B, L, E] layout
    float* Og = g_attn + ((size_t)b * L + l0) * E + h * D;
    #pragma unroll
    for (int i = 0; i < 4; ++i) {
        float inv = 1.0f / lrow[i];
        float4 r;
        r.x = o[i][0] * inv; r.y = o[i][1] * inv;
        r.z = o[i][2] * inv; r.w = o[i][3] * inv;
        *(float4*)(Og + (size_t)((ty << 2) + i) * E + (tx << 2)) = r;
    }
}

// ---------------- launch ---------------------------------------------------
extern "C" void kernel_launch(void* const* d_in, const int* in_sizes, int n_in,
                              void* d_out, int out_size) {
    const float* q_in  = (const float*)d_in[0];
    const float* k_in  = (const float*)d_in[1];
    const float* v_in  = (const float*)d_in[2];
    const float* bias  = (const float*)d_in[3];
    const float* mask  = (const float*)d_in[4];
    const float* Wqkv  = (const float*)d_in[5];
    const float* bqkv  = (const float*)d_in[6];
    const float* Wo    = (const float*)d_in[7];
    const float* bo    = (const float*)d_in[8];
    float* out = (float*)d_out;

    (void)in_sizes; (void)n_in; (void)out_size;

    // mask + bias precompute: L*S/4 threads
    mb_kernel<<<(L * S / 4) / 256, 256>>>(bias, mask);

    // fused QKV projection
    qkv_gemm<<<dim3((B * L) / BM, (3 * E) / BN), 256>>>(q_in, k_in, v_in, Wqkv, bqkv);

    // flash attention
    size_t attn_smem = (size_t)4 * 64 * LDT * sizeof(float);   // ~69.6 KB
    cudaFuncSetAttribute(attn_kernel, cudaFuncAttributeMaxDynamicSharedMemorySize,
                         (int)attn_smem);
    attn_kernel<<<dim3(L / 64, H, B), 256, attn_smem>>>();

    // output projection
    out_gemm<<<dim3((B * L) / BM, E / BN), 256>>>(Wo, bo, out);
}